// round 11
// baseline (speedup 1.0000x reference)
#include <cuda_runtime.h>
#include <cuda_bf16.h>
#include <cstdint>
#include <cstring>

// ---------------- problem constants ----------------
#define DIN   512
#define DOUT  512
#define BM    128              // rows per CTA; CTA covers full N=512
#define THREADS 256
#define MBLOCKS 512            // 65536 / BM

// smem strides chosen for conflict-free ldmatrix (16B-row phases hit 32 banks)
#define A_STRIDE 528           // 512 int8 + 16 pad  (bank offsets 4j -> full coverage)
#define B_STRIDE 80            // 64 int8 + 16 pad   (bank offsets 20j mod 32 -> distinct)

#define OFF_S   0                      // s[512] float
#define OFF_BQ  2048                   // bq[512] float
#define OFF_A   4096                   // A tile 128 x 528 = 67584
#define OFF_B0  (OFF_A + BM * A_STRIDE)        // 71680
#define OFF_B1  (OFF_B0 + BM * B_STRIDE)       // 81920
#define SMEM_BYTES (OFF_B1 + BM * B_STRIDE)    // 92160 -> 2 CTAs/SM

// ---------------- device scratch (no allocations allowed) ----------------
__device__ unsigned g_absmax_bits;
__device__ char     g_wq[DOUT * DIN];   // int8 quantized weights, [o][i] row-major
__device__ float    g_s[DOUT];          // act_scale * w_scale[o]
__device__ float    g_bq[DOUT];         // quantized bias (dequantized)

// ---------------- helpers ----------------
static __device__ __forceinline__ uint32_t smem_u32(const void* p) {
    uint32_t a;
    asm("{ .reg .u64 t; cvta.to.shared.u64 t, %1; cvt.u32.u64 %0, t; }" : "=r"(a) : "l"(p));
    return a;
}

#define LDMATRIX_X4(d0, d1, d2, d3, addr) \
    asm volatile("ldmatrix.sync.aligned.m8n8.x4.shared.b16 {%0,%1,%2,%3}, [%4];" \
                 : "=r"(d0), "=r"(d1), "=r"(d2), "=r"(d3) : "r"(addr))

#define MMA_S8(c, a0, a1, a2, a3, b0, b1) \
    asm volatile("mma.sync.aligned.m16n8k32.row.col.s32.s8.s8.s32 " \
                 "{%0,%1,%2,%3}, {%4,%5,%6,%7}, {%8,%9}, {%0,%1,%2,%3};" \
                 : "+r"((c)[0]), "+r"((c)[1]), "+r"((c)[2]), "+r"((c)[3]) \
                 : "r"(a0), "r"(a1), "r"(a2), "r"(a3), "r"(b0), "r"(b1))

#define CP_ASYNC16(dst, src) \
    asm volatile("cp.async.cg.shared.global [%0], [%1], 16;" :: "r"(dst), "l"(src))
#define CP_COMMIT()  asm volatile("cp.async.commit_group;" ::: "memory")
#define CP_WAIT1()   asm volatile("cp.async.wait_group 1;" ::: "memory")
#define CP_WAIT0()   asm volatile("cp.async.wait_group 0;" ::: "memory")

// ---------------- kernel 0: reset reduction scratch ----------------
__global__ void zero_kernel() { g_absmax_bits = 0u; }

// ---------------- kernel 1: global max|x| ----------------
__global__ void __launch_bounds__(256) absmax_kernel(const float* __restrict__ x, int n4) {
    const float4* x4 = (const float4*)x;
    float m = 0.f;
    for (int i = blockIdx.x * blockDim.x + threadIdx.x; i < n4; i += gridDim.x * blockDim.x) {
        float4 v = x4[i];
        m = fmaxf(m, fmaxf(fmaxf(fabsf(v.x), fabsf(v.y)), fmaxf(fabsf(v.z), fabsf(v.w))));
    }
    #pragma unroll
    for (int o = 16; o; o >>= 1) m = fmaxf(m, __shfl_xor_sync(0xFFFFFFFFu, m, o));
    __shared__ float sm[8];
    int lane = threadIdx.x & 31, w = threadIdx.x >> 5;
    if (!lane) sm[w] = m;
    __syncthreads();
    if (w == 0) {
        m = (lane < (int)(blockDim.x >> 5)) ? sm[lane] : 0.f;
        #pragma unroll
        for (int o = 4; o; o >>= 1) m = fmaxf(m, __shfl_xor_sync(0xFFFFFFFFu, m, o));
        if (!lane) atomicMax(&g_absmax_bits, __float_as_uint(m));  // |x| >= 0: uint order == float order
    }
}

// ---------------- kernel 2: per-channel weight quant (int8) + bias quant ----------------
__global__ void __launch_bounds__(128) wquant_kernel(const float* __restrict__ w,
                                                     const float* __restrict__ bias) {
    int o = blockIdx.x;
    float4 v = ((const float4*)(w + (size_t)o * DIN))[threadIdx.x];
    float m = fmaxf(fmaxf(fabsf(v.x), fabsf(v.y)), fmaxf(fabsf(v.z), fabsf(v.w)));
    #pragma unroll
    for (int off = 16; off; off >>= 1) m = fmaxf(m, __shfl_xor_sync(0xFFFFFFFFu, m, off));
    __shared__ float sm[4];
    int lane = threadIdx.x & 31, wp = threadIdx.x >> 5;
    if (!lane) sm[wp] = m;
    __syncthreads();
    m = fmaxf(fmaxf(sm[0], sm[1]), fmaxf(sm[2], sm[3]));
    float wscale = __fdiv_rn(m, 127.0f);

    // exact: rintf(fdiv_rn(w, wscale)) matches jnp.round(w/scale) (half-even), clip [-128,127]
    int q0 = (int)fminf(fmaxf(rintf(__fdiv_rn(v.x, wscale)), -128.f), 127.f);
    int q1 = (int)fminf(fmaxf(rintf(__fdiv_rn(v.y, wscale)), -128.f), 127.f);
    int q2 = (int)fminf(fmaxf(rintf(__fdiv_rn(v.z, wscale)), -128.f), 127.f);
    int q3 = (int)fminf(fmaxf(rintf(__fdiv_rn(v.w, wscale)), -128.f), 127.f);
    unsigned pk = (q0 & 0xFF) | ((q1 & 0xFF) << 8) | ((q2 & 0xFF) << 16) | ((unsigned)(q3 & 0xFF) << 24);
    *(unsigned*)(g_wq + (size_t)o * DIN + threadIdx.x * 4) = pk;

    if (threadIdx.x == 0) {
        float act = __fdiv_rn(__uint_as_float(g_absmax_bits), 127.0f);
        float s = act * wscale;                       // matches ref fp32 product
        g_s[o]  = s;
        g_bq[o] = rintf(__fdiv_rn(bias[o], s)) * s;   // 32-bit clip is a no-op at these magnitudes
    }
}

// ---------------- kernel 3: int8 mma.sync GEMM with fused activation quant ----------------
// CTA: 128 rows x N=512. A (quantized x) resident in smem; B streamed per
// 128-n block in 64-k chunks, cp.async double-buffered. 8 warps = 4(m) x 2(n),
// warp tile 32x64, mma.m16n8k32.s8, s32 accum (exact).
__global__ void __launch_bounds__(THREADS, 2)
gemm_kernel(const float* __restrict__ x, float* __restrict__ out) {
    extern __shared__ char smem[];
    const uint32_t sb = smem_u32(smem);
    const int tid    = threadIdx.x;
    const int lane   = tid & 31;
    const int wid    = tid >> 5;
    const int warp_m = wid & 3;        // 0..3 -> 32-row slice
    const int warp_n = wid >> 2;       // 0..1 -> 64-col slice (within 128-n block)
    const long long m0 = (long long)blockIdx.x * BM;

    // scales/bias -> smem
    float* s_s  = (float*)(smem + OFF_S);
    float* s_bq = (float*)(smem + OFF_BQ);
    #pragma unroll
    for (int j = 0; j < 2; ++j) { s_s[tid + j * 256] = g_s[tid + j * 256];
                                  s_bq[tid + j * 256] = g_bq[tid + j * 256]; }

    // double-float reciprocal of act_scale (exact-round fallback below)
    const float s = __fdiv_rn(__uint_as_float(g_absmax_bits), 127.0f);
    const float hi = __frcp_rn(s);
    const float lo = hi * __fmaf_rn(-hi, s, 1.0f);

    // prefetch first B chunk (n-block 0, k-chunk 0) while we quantize A
    auto prefetch_b = [&](int g) {                 // g = nb*8 + kit, buffer g&1
        const int nb = g >> 3, kit = g & 7;
        const uint32_t boff = (g & 1) ? OFF_B1 : OFF_B0;
        #pragma unroll
        for (int j = 0; j < 2; ++j) {
            int c = tid + j * 256;                 // 512 chunks of 16B
            int rw = c >> 2, ch = c & 3;
            const char* src = g_wq + (size_t)(nb * 128 + rw) * DIN + kit * 64 + ch * 16;
            CP_ASYNC16(sb + boff + rw * B_STRIDE + ch * 16, src);
        }
        CP_COMMIT();
    };
    prefetch_b(0);

    // ---- A phase: load x (fp32), quantize to int8 exactly, store to smem ----
    // q = rintf(x/s): approx via double-float 1/s; exact fdiv fallback only when
    // the quotient lands within 1e-4 of a half-integer (guarded by ballot so the
    // MUFU path is branched over, not predicated). |err| <= ~1.5e-5 << 1e-4.
    {
        const float4* xg = (const float4*)(x + m0 * DIN);
        #pragma unroll 4
        for (int j = 0; j < 64; ++j) {
            int c = tid + j * 256;                 // 16384 float4 in tile
            int row = c >> 7, wk = c & 127;
            float4 v = xg[row * 128 + wk];
            float q[4], fr[4];
            q[0] = __fmaf_rn(v.x, lo, v.x * hi);
            q[1] = __fmaf_rn(v.y, lo, v.y * hi);
            q[2] = __fmaf_rn(v.z, lo, v.z * hi);
            q[3] = __fmaf_rn(v.w, lo, v.w * hi);
            float n0 = rintf(q[0]), n1 = rintf(q[1]), n2 = rintf(q[2]), n3 = rintf(q[3]);
            fr[0] = fabsf(fabsf(q[0] - n0) - 0.5f);
            fr[1] = fabsf(fabsf(q[1] - n1) - 0.5f);
            fr[2] = fabsf(fabsf(q[2] - n2) - 0.5f);
            fr[3] = fabsf(fabsf(q[3] - n3) - 0.5f);
            bool rare = (fminf(fminf(fr[0], fr[1]), fminf(fr[2], fr[3])) < 1e-4f);
            if (__ballot_sync(0xFFFFFFFFu, rare)) {
                if (rare) {                        // exact replication of jnp.round(x/s)
                    n0 = rintf(__fdiv_rn(v.x, s));
                    n1 = rintf(__fdiv_rn(v.y, s));
                    n2 = rintf(__fdiv_rn(v.z, s));
                    n3 = rintf(__fdiv_rn(v.w, s));
                }
            }
            int i0 = (int)fminf(fmaxf(n0, -128.f), 127.f);
            int i1 = (int)fminf(fmaxf(n1, -128.f), 127.f);
            int i2 = (int)fminf(fmaxf(n2, -128.f), 127.f);
            int i3 = (int)fminf(fmaxf(n3, -128.f), 127.f);
            unsigned pk = (i0 & 0xFF) | ((i1 & 0xFF) << 8) | ((i2 & 0xFF) << 16)
                        | ((unsigned)(i3 & 0xFF) << 24);
            *(unsigned*)(smem + OFF_A + row * A_STRIDE + wk * 4) = pk;
        }
    }
    __syncthreads();   // A tile + scales visible

    // ldmatrix base addresses (x4 form: lanes 0-7 m0 rows, 8-15 m1, 16-23 m2, 24-31 m3)
    const uint32_t a_base = sb + OFF_A + (warp_m * 32 + (lane & 15)) * A_STRIDE + ((lane & 16) ? 16 : 0);
    const uint32_t b_lane = (warp_n * 64 + (lane & 15)) * B_STRIDE + ((lane & 16) ? 16 : 0);

    uint32_t acc[2][8][4];
    #pragma unroll
    for (int mt = 0; mt < 2; ++mt)
        #pragma unroll
        for (int nt = 0; nt < 8; ++nt)
            #pragma unroll
            for (int r = 0; r < 4; ++r) acc[mt][nt][r] = 0u;

    // ---- mainloop: 4 n-blocks x 8 k-chunks ----
    #pragma unroll 1
    for (int g = 0; g < 32; ++g) {
        if (g + 1 < 32) { prefetch_b(g + 1); CP_WAIT1(); } else { CP_WAIT0(); }
        __syncthreads();                         // chunk g ready for everyone

        const uint32_t bbase = sb + ((g & 1) ? OFF_B1 : OFF_B0) + b_lane;
        const uint32_t abase = a_base + (g & 7) * 64;
        #pragma unroll
        for (int ks = 0; ks < 2; ++ks) {         // two K=32 steps per 64-k chunk
            uint32_t a0[4], a1[4];
            LDMATRIX_X4(a0[0], a0[1], a0[2], a0[3], abase + ks * 32);
            LDMATRIX_X4(a1[0], a1[1], a1[2], a1[3], abase + ks * 32 + 16 * A_STRIDE);
            #pragma unroll
            for (int ng = 0; ng < 4; ++ng) {     // 16 n-cols per ldmatrix.x4
                uint32_t b[4];
                LDMATRIX_X4(b[0], b[1], b[2], b[3], bbase + ks * 32 + ng * 16 * B_STRIDE);
                MMA_S8(acc[0][2 * ng],     a0[0], a0[1], a0[2], a0[3], b[0], b[2]);
                MMA_S8(acc[0][2 * ng + 1], a0[0], a0[1], a0[2], a0[3], b[1], b[3]);
                MMA_S8(acc[1][2 * ng],     a1[0], a1[1], a1[2], a1[3], b[0], b[2]);
                MMA_S8(acc[1][2 * ng + 1], a1[0], a1[1], a1[2], a1[3], b[1], b[3]);
            }
        }
        __syncthreads();                         // all reads done before buffer reuse

        if ((g & 7) == 7) {                      // n-block finished -> epilogue + reset
            const int nb = g >> 3;
            #pragma unroll
            for (int mt = 0; mt < 2; ++mt) {
                const long long rbase = m0 + warp_m * 32 + mt * 16 + (lane >> 2);
                #pragma unroll
                for (int nt = 0; nt < 8; ++nt) {
                    const int col = nb * 128 + warp_n * 64 + nt * 8 + (lane & 3) * 2;
                    const float sv0 = s_s[col],  sv1 = s_s[col + 1];
                    const float bv0 = s_bq[col], bv1 = s_bq[col + 1];
                    float2 o0, o1;
                    o0.x = (float)(int)acc[mt][nt][0] * sv0 + bv0;
                    o0.y = (float)(int)acc[mt][nt][1] * sv1 + bv1;
                    o1.x = (float)(int)acc[mt][nt][2] * sv0 + bv0;
                    o1.y = (float)(int)acc[mt][nt][3] * sv1 + bv1;
                    __stcs((float2*)(out + rbase * DOUT + col), o0);
                    __stcs((float2*)(out + (rbase + 8) * DOUT + col), o1);
                    acc[mt][nt][0] = acc[mt][nt][1] = acc[mt][nt][2] = acc[mt][nt][3] = 0u;
                }
            }
        }
    }
}

// ---------------- host launcher ----------------
extern "C" void kernel_launch(void* const* d_in, const int* in_sizes, int n_in,
                              void* d_out, int out_size) {
    const float* x    = (const float*)d_in[0];
    const float* w    = (const float*)d_in[1];
    const float* bias = (const float*)d_in[2];
    float* out = (float*)d_out;

    zero_kernel<<<1, 1>>>();
    absmax_kernel<<<1216, 256>>>(x, in_sizes[0] / 4);   // 8 x 152 SMs (GB300)
    wquant_kernel<<<DOUT, 128>>>(w, bias);

    cudaFuncSetAttribute(gemm_kernel, cudaFuncAttributeMaxDynamicSharedMemorySize, SMEM_BYTES);
    gemm_kernel<<<MBLOCKS, THREADS, SMEM_BYTES>>>(x, out);
}